// round 14
// baseline (speedup 1.0000x reference)
#include <cuda_runtime.h>
#include <cuda_fp16.h>
#include <cstdint>
#include <math.h>

#define ORDER   8
#define IN_SZ   512
#define OUT_SZ  512
#define BATCH   4096
#define KK      4096              // inner dim (k=1..8 folded; k=0 -> bias)
#define BM      128
#define BN      128
#define BK      64
#define NTILE   (KK / BK)         // 64 k-chunks
#define STAGES  4

// single fp16 operands: J rounding + W rounding each ~2^-12 rms, independent
__device__ __align__(256) __half g_J[(size_t)BATCH  * KK];
__device__ __align__(256) __half g_W[(size_t)OUT_SZ * KK];
__device__ float g_bias[OUT_SZ];

// ---------------------------------------------------------------------------
// helpers (baseline PTX only: cp.async / ldmatrix / mma.sync — no tcgen05)
// ---------------------------------------------------------------------------
__device__ __forceinline__ uint32_t s2u(const void* p) {
    uint32_t a;
    asm("{ .reg .u64 t; cvta.to.shared.u64 t, %1; cvt.u32.u64 %0, t; }"
        : "=r"(a) : "l"(p));
    return a;
}

#define SWZ(x) ((x) ^ (((x) >> 3) & 0x70))   // 128B-row xor swizzle

#define CP16(dst, src) \
    asm volatile("cp.async.cg.shared.global [%0], [%1], 16;" \
                 :: "r"(dst), "l"(__cvta_generic_to_global(src)) : "memory")

#define LDSM4(r0, r1, r2, r3, addr) \
    asm volatile("ldmatrix.sync.aligned.m8n8.x4.shared.b16 {%0,%1,%2,%3}, [%4];" \
                 : "=r"(r0), "=r"(r1), "=r"(r2), "=r"(r3) : "r"(addr))

#define MMA(c, a, b0, b1) \
    asm volatile("mma.sync.aligned.m16n8k16.row.col.f32.f16.f16.f32 " \
                 "{%0,%1,%2,%3},{%4,%5,%6,%7},{%8,%9},{%0,%1,%2,%3};" \
                 : "+f"((c)[0]), "+f"((c)[1]), "+f"((c)[2]), "+f"((c)[3]) \
                 : "r"((a)[0]), "r"((a)[1]), "r"((a)[2]), "r"((a)[3]), \
                   "r"(b0), "r"(b1))

// ---------------------------------------------------------------------------
// Kernel 1 (fused prep): blocks [0,512) -> W fold + bias (smem-staged, coalesced)
//                        blocks [512, 4608) -> Jacobi values (fp16)
// ---------------------------------------------------------------------------
__global__ void __launch_bounds__(256) prep_kernel(const float* __restrict__ w,
                                                   const float* __restrict__ coeff,
                                                   const float* __restrict__ x) {
    __shared__ float sc[IN_SZ * 9 + IN_SZ + 256];   // coeff slice + w row + red
    const int tid = threadIdx.x;

    if (blockIdx.x < OUT_SZ) {
        // ---------------- W prep ----------------
        const int o = blockIdx.x;
        float* scoef = sc;
        float* swr   = sc + IN_SZ * 9;
        float* red   = swr + IN_SZ;

        for (int j = tid; j < IN_SZ * 9; j += 256)
            scoef[j] = coeff[(size_t)o * (IN_SZ * 9) + j];
        for (int j = tid; j < IN_SZ; j += 256)
            swr[j] = w[o * IN_SZ + j];
        __syncthreads();

        const int i0 = tid * 2;          // two adjacent inputs per thread
        const float w0 = swr[i0], w1 = swr[i0 + 1];
        float acc = scoef[i0 * 9] * w0 + scoef[(i0 + 1) * 9] * w1;
#pragma unroll
        for (int k = 1; k <= ORDER; k++) {
            const __half h0 = __float2half_rn(scoef[i0 * 9 + k] * w0);
            const __half h1 = __float2half_rn(scoef[(i0 + 1) * 9 + k] * w1);
            *(__half2*)(g_W + (size_t)o * KK + (size_t)(k - 1) * IN_SZ + i0) =
                __halves2half2(h0, h1);
        }
        red[tid] = acc;
        __syncthreads();
        for (int s = 128; s > 0; s >>= 1) {
            if (tid < s) red[tid] += red[tid + s];
            __syncthreads();
        }
        if (tid == 0) g_bias[o] = red[0];
    } else {
        // ---------------- J gen ----------------
        const int g = (blockIdx.x - OUT_SZ) * 256 + tid;
        const int e = g * 2;
        const int b = e >> 9;
        const int i = e & (IN_SZ - 1);
        const float2 xv = *(const float2*)(x + e);
        const float t0 = tanhf(xv.x);
        const float t1 = tanhf(xv.y);

        const size_t base = (size_t)b * KK + i;
        float pm0 = 1.0f, pm1 = 1.0f;
        float p0 = 2.0f * t0, p1 = 2.0f * t1;

        *(__half2*)(g_J + base) =
            __halves2half2(__float2half_rn(p0), __float2half_rn(p1));
#pragma unroll
        for (int n = 2; n <= ORDER; n++) {
            const double a = 1.0, bb = 1.0;
            const float k1 = (float)((2.0 * n + a + bb) * (2.0 * n + a + bb - 1.0) /
                                     (2.0 * n * (n + a + bb)));
            const float k2 = (float)((2.0 * n + a + bb - 1.0) * (a * a - bb * bb) /
                                     (2.0 * n * (n + a + bb) * (2.0 * n + a + bb - 2.0)));
            const float k3 = (float)((n + a - 1.0) * (n + bb - 1.0) * (2.0 * n + a + bb) /
                                     (n * (n + a + bb) * (2.0 * n + a + bb - 2.0)));
            const float pn0 = (k1 * t0 + k2) * p0 - k3 * pm0;
            const float pn1 = (k1 * t1 + k2) * p1 - k3 * pm1;
            pm0 = p0; pm1 = p1;
            p0 = pn0; p1 = pn1;
            *(__half2*)(g_J + base + (size_t)(n - 1) * IN_SZ) =
                __halves2half2(__float2half_rn(p0), __float2half_rn(p1));
        }
    }
}

// ---------------------------------------------------------------------------
// Kernel 2: HMMA GEMM, warp-split-K. C[b][o] = bias[o] + J[b]·W[o]
// 128x128x64 CTA tile, 4-stage cp.async. 8 warps = 2(M) x 2(N) x 2(K):
// each warp 64x64 tile over half the k-chunk; pairwise smem reduction at end.
// smem stage s at base + s*32768: {A=J (16KB), W (16KB)}, SWZ rows of 128B
// ---------------------------------------------------------------------------
#define SLOT_BYTES 32768
#define SMEM_TOTAL (STAGES * SLOT_BYTES + 1024)

__global__ void __launch_bounds__(256, 1) gemm_hmma(float* __restrict__ C) {
    extern __shared__ __align__(1024) char smem_raw[];
    const uint32_t sbr = s2u(smem_raw);
    const uint32_t ab = (sbr + 1023u) & ~1023u;   // 1024-aligned smem base
    char* smem = smem_raw + (ab - sbr);

    const int tid  = threadIdx.x;
    const int wid  = tid >> 5;
    const int lane = tid & 31;
    const int bm = blockIdx.y * BM;
    const int bn = blockIdx.x * BN;

    const int wk = wid & 1;                 // K half (0/1)
    const int wn = ((wid >> 1) & 1) * 64;   // N offset
    const int wm = ((wid >> 2) & 1) * 64;   // M offset

    // ---- cp.async mapping: 2 tiles x 1024 16B-chunks / 256 threads
    uint32_t dsw[4], aoff[4], boff[4];      // element offsets fit in u32
#pragma unroll
    for (int j = 0; j < 4; j++) {
        const int c = tid + 256 * j;
        const int row = c >> 3;
        const int col = c & 7;
        dsw[j] = SWZ((uint32_t)(row * 128 + col * 16));
        aoff[j] = (uint32_t)((bm + row) * KK + col * 8);
        boff[j] = (uint32_t)((bn + row) * KK + col * 8);
    }

    auto load_tile = [&](int kt, int s) {
        const uint32_t base = ab + (uint32_t)s * SLOT_BYTES;
        const uint32_t ko = (uint32_t)kt * BK;
#pragma unroll
        for (int j = 0; j < 4; j++) {
            CP16(base +          dsw[j], g_J + (size_t)(aoff[j] + ko));
            CP16(base + 16384u + dsw[j], g_W + (size_t)(boff[j] + ko));
        }
        asm volatile("cp.async.commit_group;" ::: "memory");
    };

    // ---- ldmatrix per-lane address pre-terms (4 m-blocks, 4 n16-blocks)
    const uint32_t ahi = (uint32_t)(lane >> 4);
    uint32_t aTerm[4], aRk[4];
#pragma unroll
    for (int mb = 0; mb < 4; mb++) {
        const uint32_t ra = (uint32_t)(wm + mb * 16 + (lane & 15));
        aTerm[mb] = ra * 128u;
        aRk[mb]   = ra & 7u;
    }
    const uint32_t bhi = (uint32_t)((lane >> 3) & 1);
    uint32_t bTerm[4], bRk[4];
#pragma unroll
    for (int p = 0; p < 4; p++) {
        const uint32_t rb = (uint32_t)(wn + p * 16 + ((lane >> 4) << 3) + (lane & 7));
        bTerm[p] = rb * 128u;
        bRk[p]   = rb & 7u;
    }

    float acc[4][8][4];
#pragma unroll
    for (int mb = 0; mb < 4; mb++)
#pragma unroll
        for (int nb = 0; nb < 8; nb++)
#pragma unroll
            for (int q = 0; q < 4; q++) acc[mb][nb][q] = 0.f;

    // prologue: stages 0..2 (keep 1 slot free)
    load_tile(0, 0);
    load_tile(1, 1);
    load_tile(2, 2);

#pragma unroll 1
    for (int kt = 0; kt < NTILE; kt++) {
        if (kt < NTILE - 2)       asm volatile("cp.async.wait_group 2;" ::: "memory");
        else if (kt == NTILE - 2) asm volatile("cp.async.wait_group 1;" ::: "memory");
        else                      asm volatile("cp.async.wait_group 0;" ::: "memory");
        __syncthreads();

        if (kt + 3 < NTILE) load_tile(kt + 3, (kt + 3) % STAGES);

        const uint32_t sb = ab + (uint32_t)(kt % STAGES) * SLOT_BYTES;

        // this warp covers k16-chunks [2*wk, 2*wk+1] of the 4 in BK=64
#pragma unroll
        for (int ks = 0; ks < 2; ks++) {
            const uint32_t kcA = 4u * (uint32_t)wk + 2u * ks + ahi;  // k8 index
            const uint32_t kcB = 4u * (uint32_t)wk + 2u * ks + bhi;

            uint32_t av[4][4];
#pragma unroll
            for (int mb = 0; mb < 4; mb++) {
                const uint32_t off = aTerm[mb] + ((kcA ^ aRk[mb]) << 4);
                LDSM4(av[mb][0], av[mb][1], av[mb][2], av[mb][3], sb + off);
            }

#pragma unroll
            for (int p = 0; p < 4; p++) {
                const uint32_t off = bTerm[p] + ((kcB ^ bRk[p]) << 4);
                uint32_t bv[4];
                LDSM4(bv[0], bv[1], bv[2], bv[3], sb + 16384u + off);
#pragma unroll
                for (int mb = 0; mb < 4; mb++) {
                    MMA(acc[mb][2 * p],     av[mb], bv[0], bv[1]);
                    MMA(acc[mb][2 * p + 1], av[mb], bv[2], bv[3]);
                }
            }
        }
    }
    __syncthreads();   // all MMA work done; smem slots reusable for reduction

    // ---- pairwise K-reduction through smem (wk=1 writes, wk=0 adds+stores)
    char* rp = smem + (wid >> 1) * 16384;   // 16KB per (wm,wn) pair
    if (wk == 1) {
#pragma unroll
        for (int mb = 0; mb < 4; mb++)
#pragma unroll
            for (int nb = 0; nb < 8; nb++)
                *(float4*)(rp + ((mb * 8 + nb) * 32 + lane) * 16) =
                    make_float4(acc[mb][nb][0], acc[mb][nb][1],
                                acc[mb][nb][2], acc[mb][nb][3]);
    }
    __syncthreads();
    if (wk == 0) {
#pragma unroll
        for (int mb = 0; mb < 4; mb++) {
            const int row0 = bm + wm + mb * 16 + (lane >> 2);
#pragma unroll
            for (int nb = 0; nb < 8; nb++) {
                const float4 v = *(const float4*)(rp + ((mb * 8 + nb) * 32 + lane) * 16);
                const int cn = bn + wn + nb * 8 + (lane & 3) * 2;
                const float b0 = g_bias[cn];
                const float b1 = g_bias[cn + 1];
                float2 v0 = make_float2(acc[mb][nb][0] + v.x + b0,
                                        acc[mb][nb][1] + v.y + b1);
                float2 v1 = make_float2(acc[mb][nb][2] + v.z + b0,
                                        acc[mb][nb][3] + v.w + b1);
                *(float2*)(C + (size_t)row0 * OUT_SZ + cn)       = v0;
                *(float2*)(C + (size_t)(row0 + 8) * OUT_SZ + cn) = v1;
            }
        }
    }
}

// ---------------------------------------------------------------------------
extern "C" void kernel_launch(void* const* d_in, const int* in_sizes, int n_in,
                              void* d_out, int out_size) {
    const float* x       = (const float*)d_in[0];  // [4096, 512]
    const float* weights = (const float*)d_in[1];  // [512, 512]
    const float* coeff   = (const float*)d_in[2];  // [512, 512, 9]
    float* out = (float*)d_out;                    // [4096, 512]

    cudaFuncSetAttribute(gemm_hmma, cudaFuncAttributeMaxDynamicSharedMemorySize,
                         SMEM_TOTAL);

    prep_kernel<<<OUT_SZ + (BATCH * IN_SZ / 2) / 256, 256>>>(weights, coeff, x);
    dim3 grid(OUT_SZ / BN, BATCH / BM);
    gemm_hmma<<<grid, 256, SMEM_TOTAL>>>(out);
}